// round 1
// baseline (speedup 1.0000x reference)
#include <cuda_runtime.h>
#include <cstdint>

#define B_ 8
#define T_ 4096
#define D_ 512
#define H_ 512
#define M_ (B_*T_)      // 32768 rows
#define NC 64           // chunks per sequence
#define LC (T_/NC)      // 64 steps per chunk

// Scratch (device globals; no runtime allocation)
__device__ float g_C[(size_t)M_*H_];   // c_t = sigmoid(-k) = 1 - z
__device__ float g_G[(size_t)M_*H_];   // g(pre_h)
__device__ float g_A[B_*NC*H_];        // per-chunk decay product
__device__ float g_S[B_*NC*H_];        // per-chunk local scan value
__device__ float g_Hb[B_*NC*H_];       // chunk-boundary states

__device__ __forceinline__ float sigmoidf_(float x) {
    return 1.0f / (1.0f + __expf(-x));
}

__device__ __forceinline__ uint32_t f2tf32(float f) {
    uint32_t u;
    asm volatile("cvt.rna.tf32.f32 %0, %1;" : "=r"(u) : "f"(f));
    return u;
}

__device__ __forceinline__ void mma_tf32(float d[4], const uint32_t a[4], const uint32_t b[2]) {
    asm volatile(
        "mma.sync.aligned.m16n8k8.row.col.f32.tf32.tf32.f32 "
        "{%0,%1,%2,%3}, {%4,%5,%6,%7}, {%8,%9}, {%0,%1,%2,%3};\n"
        : "+f"(d[0]), "+f"(d[1]), "+f"(d[2]), "+f"(d[3])
        : "r"(a[0]), "r"(a[1]), "r"(a[2]), "r"(a[3]), "r"(b[0]), "r"(b[1]));
}

// ------------------------- Fused GEMM + activation -------------------------
// C[m][n] = sum_k x[m][k] * W[n][k]   (W = Wz for n<512, Wh for n>=512)
// Epilogue: n<512 -> g_C = sigmoid(-(C+bz)); n>=512 -> g_G = g(C+bh)
#define BM 128
#define BN 128
#define BK 16
#define KCHUNKS (D_/BK)   // 32

__global__ __launch_bounds__(256) void gemm_act_kernel(
    const float* __restrict__ x,
    const float* __restrict__ Wz, const float* __restrict__ bz,
    const float* __restrict__ Wh, const float* __restrict__ bh)
{
    __shared__ uint32_t As[2][BM][BK + 4];
    __shared__ uint32_t Bs[2][BN][BK + 4];

    const int tid  = threadIdx.x;
    const int warp = tid >> 5;
    const int lane = tid & 31;
    const int wm = warp >> 2;   // 0..1 (64 rows each)
    const int wn = warp & 3;    // 0..3 (32 cols each)

    const int bn = blockIdx.x;  // 0..7 (N tiles over fused N=1024)
    const int bm = blockIdx.y;  // 0..255
    const bool isZ = (bn < 4);
    const float* __restrict__ Wp = isZ ? Wz : Wh;
    const int nbase = (isZ ? bn : bn - 4) * BN;  // 0..384 within the 512-col buffer
    const int m0 = bm * BM;

    float acc[4][4][4];
    #pragma unroll
    for (int i = 0; i < 4; i++)
        #pragma unroll
        for (int j = 0; j < 4; j++)
            #pragma unroll
            for (int r = 0; r < 4; r++) acc[i][j][r] = 0.f;

    const int lrow = tid >> 2;   // 0..63
    const int lvec = tid & 3;    // 0..3 (which float4 of the 16-float row)

    float4 ra[2], rb[2];

    // prefetch chunk 0
    #pragma unroll
    for (int i = 0; i < 2; i++) {
        int row = lrow + i * 64;
        ra[i] = *reinterpret_cast<const float4*>(x  + (size_t)(m0 + row) * D_ + lvec * 4);
        rb[i] = *reinterpret_cast<const float4*>(Wp + (size_t)(nbase + row) * D_ + lvec * 4);
    }
    // stash into buffer 0
    #pragma unroll
    for (int i = 0; i < 2; i++) {
        int row = lrow + i * 64;
        uint4 ua = make_uint4(f2tf32(ra[i].x), f2tf32(ra[i].y), f2tf32(ra[i].z), f2tf32(ra[i].w));
        uint4 ub = make_uint4(f2tf32(rb[i].x), f2tf32(rb[i].y), f2tf32(rb[i].z), f2tf32(rb[i].w));
        *reinterpret_cast<uint4*>(&As[0][row][lvec * 4]) = ua;
        *reinterpret_cast<uint4*>(&Bs[0][row][lvec * 4]) = ub;
    }
    __syncthreads();

    for (int kc = 0; kc < KCHUNKS; kc++) {
        const int buf = kc & 1;
        float4 na[2], nb[2];
        if (kc + 1 < KCHUNKS) {
            const int koff = (kc + 1) * BK;
            #pragma unroll
            for (int i = 0; i < 2; i++) {
                int row = lrow + i * 64;
                na[i] = *reinterpret_cast<const float4*>(x  + (size_t)(m0 + row) * D_ + koff + lvec * 4);
                nb[i] = *reinterpret_cast<const float4*>(Wp + (size_t)(nbase + row) * D_ + koff + lvec * 4);
            }
        }

        // compute on current buffer: two k8 sub-steps
        #pragma unroll
        for (int ks = 0; ks < 2; ks++) {
            uint32_t af[4][4];
            uint32_t bf[4][2];
            const int arow = wm * 64 + (lane >> 2);
            const int acol = ks * 8 + (lane & 3);
            #pragma unroll
            for (int mt = 0; mt < 4; mt++) {
                af[mt][0] = As[buf][arow + mt * 16][acol];
                af[mt][1] = As[buf][arow + mt * 16 + 8][acol];
                af[mt][2] = As[buf][arow + mt * 16][acol + 4];
                af[mt][3] = As[buf][arow + mt * 16 + 8][acol + 4];
            }
            const int brow = wn * 32 + (lane >> 2);
            const int bcol = ks * 8 + (lane & 3);
            #pragma unroll
            for (int nt = 0; nt < 4; nt++) {
                bf[nt][0] = Bs[buf][brow + nt * 8][bcol];
                bf[nt][1] = Bs[buf][brow + nt * 8][bcol + 4];
            }
            #pragma unroll
            for (int mt = 0; mt < 4; mt++)
                #pragma unroll
                for (int nt = 0; nt < 4; nt++)
                    mma_tf32(acc[mt][nt], af[mt], bf[nt]);
        }

        if (kc + 1 < KCHUNKS) {
            const int nbuf = buf ^ 1;
            #pragma unroll
            for (int i = 0; i < 2; i++) {
                int row = lrow + i * 64;
                uint4 ua = make_uint4(f2tf32(na[i].x), f2tf32(na[i].y), f2tf32(na[i].z), f2tf32(na[i].w));
                uint4 ub = make_uint4(f2tf32(nb[i].x), f2tf32(nb[i].y), f2tf32(nb[i].z), f2tf32(nb[i].w));
                *reinterpret_cast<uint4*>(&As[nbuf][row][lvec * 4]) = ua;
                *reinterpret_cast<uint4*>(&Bs[nbuf][row][lvec * 4]) = ub;
            }
        }
        __syncthreads();
    }

    // Epilogue: bias + activation, write to scratch
    float* __restrict__ outBuf = isZ ? g_C : g_G;
    const float* __restrict__ bias = isZ ? bz : bh;
    const int row0 = m0 + wm * 64 + (lane >> 2);
    const int col0 = wn * 32 + 2 * (lane & 3);

    #pragma unroll
    for (int mt = 0; mt < 4; mt++) {
        #pragma unroll
        for (int nt = 0; nt < 4; nt++) {
            const int c = nbase + col0 + nt * 8;     // 0..511 within buffer
            const float b0v = bias[c];
            const float b1v = bias[c + 1];
            #pragma unroll
            for (int half = 0; half < 2; half++) {
                const int rr = row0 + mt * 16 + half * 8;
                float v0 = acc[mt][nt][half * 2 + 0] + b0v;
                float v1 = acc[mt][nt][half * 2 + 1] + b1v;
                float o0, o1;
                if (isZ) {
                    o0 = sigmoidf_(-v0);            // c = 1 - z
                    o1 = sigmoidf_(-v1);
                } else {
                    o0 = (v0 >= 0.f) ? (v0 + 0.5f) : sigmoidf_(v0);   // g(x)
                    o1 = (v1 >= 0.f) ? (v1 + 0.5f) : sigmoidf_(v1);
                }
                *reinterpret_cast<float2*>(&outBuf[(size_t)rr * H_ + c]) = make_float2(o0, o1);
            }
        }
    }
}

// ------------------------- Scan phase A: per-chunk reduce -------------------------
__global__ __launch_bounds__(256) void scan_phaseA()
{
    const int idx = blockIdx.x * 256 + threadIdx.x;     // 0 .. B*NC*H-1
    const int h  = idx & (H_ - 1);
    const int ch = (idx >> 9) & (NC - 1);
    const int b  = idx >> 15;
    const size_t base = ((size_t)(b * T_ + ch * LC)) * H_ + h;

    float A = 1.f, s = 0.f;
    #pragma unroll 8
    for (int t = 0; t < LC; t++) {
        const float c = g_C[base + (size_t)t * H_];
        const float g = g_G[base + (size_t)t * H_];
        s = c * s + (1.f - c) * g;
        A *= c;
    }
    g_A[idx] = A;
    g_S[idx] = s;
}

// ------------------------- Scan phase B: chunk-level sequential combine ------------
__global__ __launch_bounds__(256) void scan_phaseB(const float* __restrict__ h0)
{
    const int idx = blockIdx.x * 256 + threadIdx.x;     // 0 .. B*H-1 (4096)
    const int b = idx >> 9;
    const int h = idx & (H_ - 1);
    const float v = h0[b * H_ + h];
    float state = (v >= 0.f) ? (v + 0.5f) : sigmoidf_(v);   // g(h_0)

    #pragma unroll 4
    for (int ch = 0; ch < NC; ch++) {
        const int o = (b * NC + ch) * H_ + h;
        g_Hb[o] = state;
        state = g_A[o] * state + g_S[o];
    }
}

// ------------------------- Scan phase C: per-chunk rescan + write output -----------
__global__ __launch_bounds__(256) void scan_phaseC(float* __restrict__ out)
{
    const int idx = blockIdx.x * 256 + threadIdx.x;
    const int h  = idx & (H_ - 1);
    const int ch = (idx >> 9) & (NC - 1);
    const int b  = idx >> 15;
    const size_t base = ((size_t)(b * T_ + ch * LC)) * H_ + h;

    float state = g_Hb[idx];
    #pragma unroll 8
    for (int t = 0; t < LC; t++) {
        const float c = g_C[base + (size_t)t * H_];
        const float g = g_G[base + (size_t)t * H_];
        state = c * state + (1.f - c) * g;
        out[base + (size_t)t * H_] = state;
    }
}

extern "C" void kernel_launch(void* const* d_in, const int* in_sizes, int n_in,
                              void* d_out, int out_size)
{
    const float* x  = (const float*)d_in[0];
    const float* h0 = (const float*)d_in[1];
    const float* Wz = (const float*)d_in[2];
    const float* bz = (const float*)d_in[3];
    const float* Wh = (const float*)d_in[4];
    const float* bh = (const float*)d_in[5];
    float* out = (float*)d_out;

    gemm_act_kernel<<<dim3(8, 256), 256>>>(x, Wz, bz, Wh, bh);
    scan_phaseA<<<(B_ * NC * H_) / 256, 256>>>();
    scan_phaseB<<<(B_ * H_) / 256, 256>>>(h0);
    scan_phaseC<<<(B_ * NC * H_) / 256, 256>>>(out);
}

// round 3
// speedup vs baseline: 1.1651x; 1.1651x over previous
#include <cuda_runtime.h>
#include <cstdint>

#define B_ 8
#define T_ 4096
#define D_ 512
#define H_ 512
#define M_ (B_*T_)      // 32768 rows
#define NC 64
#define LC (T_/NC)      // 64

// ----------------------------- scratch (device globals) -----------------------------
// Packed fragment-order operands (tf32-rounded)
__device__ float g_Xp[(size_t)M_*D_];   // [M/16][D/8][128]  (16m x 8k blocks)
__device__ float g_Wp[1024*512];        // [N/8][D/8][64]    (8n x 8k blocks, fused [Wz;Wh])
__device__ float g_C[(size_t)M_*H_];    // c_t = sigmoid(-k)
__device__ float g_G[(size_t)M_*H_];    // g(pre_h)
__device__ float g_A[B_*NC*H_];
__device__ float g_S[B_*NC*H_];
__device__ float g_Hb[B_*NC*H_];

__device__ __forceinline__ float sigmoidf_(float x) { return 1.0f / (1.0f + __expf(-x)); }

__device__ __forceinline__ float f2tf32f(float f) {
    uint32_t u;
    asm volatile("cvt.rna.tf32.f32 %0, %1;" : "=r"(u) : "f"(f));
    return __uint_as_float(u);
}

__device__ __forceinline__ void mma_tf32(float d[4], const uint32_t a[4], const uint32_t b[2]) {
    asm volatile(
        "mma.sync.aligned.m16n8k8.row.col.f32.tf32.tf32.f32 "
        "{%0,%1,%2,%3}, {%4,%5,%6,%7}, {%8,%9}, {%0,%1,%2,%3};\n"
        : "+f"(d[0]), "+f"(d[1]), "+f"(d[2]), "+f"(d[3])
        : "r"(a[0]), "r"(a[1]), "r"(a[2]), "r"(a[3]), "r"(b[0]), "r"(b[1]));
}

#define CP_ASYNC16(sa, gp) asm volatile("cp.async.cg.shared.global [%0], [%1], 16;" :: "r"(sa), "l"(__cvta_generic_to_global(gp)) : "memory")
#define CP_COMMIT()        asm volatile("cp.async.commit_group;" ::: "memory")
#define CP_WAIT2()         asm volatile("cp.async.wait_group 2;" ::: "memory")

__device__ __forceinline__ uint32_t smem_u32(const void* p) {
    uint32_t a;
    asm("{ .reg .u64 t; cvta.to.shared.u64 t, %1; cvt.u32.u64 %0, t; }" : "=r"(a) : "l"(p));
    return a;
}

// ----------------------------- prep: tf32-round + fragment pack -----------------------------
// One warp handles one block.
//   x blocks:  16m x 8k. Lane (r=lane>>2, c=lane&3) packs {A[r][c], A[r+8][c], A[r][c+4], A[r+8][c+4]}
//              -> float4 at g_Xp[block*128 + lane*4]
//   W blocks:  8n x 8k.  Lane packs {B[r][c], B[r][c+4]} -> float2 at g_Wp[block*64 + lane*2]
#define XBLOCKS ((M_/16)*(D_/8))     // 131072
#define WBLOCKS ((1024/8)*(D_/8))    // 8192

__global__ __launch_bounds__(256) void prep_kernel(
    const float* __restrict__ x, const float* __restrict__ Wz, const float* __restrict__ Wh)
{
    const int gw   = blockIdx.x * 8 + (threadIdx.x >> 5);
    const int lane = threadIdx.x & 31;
    const int r = lane >> 2, c = lane & 3;

    if (gw < XBLOCKS) {
        const int mb = gw >> 6;          // D_/8 = 64 k-blocks per m-block row
        const int kb = gw & 63;
        const float* xp = x + (size_t)(mb * 16) * D_ + kb * 8;
        float4 v;
        v.x = f2tf32f(xp[(size_t)r * D_ + c]);
        v.y = f2tf32f(xp[(size_t)(r + 8) * D_ + c]);
        v.z = f2tf32f(xp[(size_t)r * D_ + c + 4]);
        v.w = f2tf32f(xp[(size_t)(r + 8) * D_ + c + 4]);
        reinterpret_cast<float4*>(g_Xp)[(size_t)gw * 32 + lane] = v;
    } else {
        const int wb = gw - XBLOCKS;     // 0..8191
        const int nb = wb >> 6;
        const int kb = wb & 63;
        const int n = nb * 8 + r;        // fused n in [0,1024)
        const float* Wrow = (n < 512) ? (Wz + (size_t)n * D_) : (Wh + (size_t)(n - 512) * D_);
        float2 v;
        v.x = f2tf32f(Wrow[kb * 8 + c]);
        v.y = f2tf32f(Wrow[kb * 8 + c + 4]);
        reinterpret_cast<float2*>(g_Wp)[(size_t)wb * 32 + lane] = v;
    }
}

// ----------------------------- GEMM + activation (mma.sync tf32, cp.async pipe) ---------------
// CTA tile: 128m x 128n, K staged 16 at a time (32 stages), 4 smem buffers.
// Warp tile: 64m x 32n (wm in 0..1, wn in 0..3).
#define KSTAGES 32
#define NBUF 4
#define A_STAGE_BYTES 8192      // 8 mblocks x 2 kblocks x 512B
#define B_STAGE_BYTES 8192      // 16 nblocks x 2 kblocks x 256B
#define STAGE_BYTES (A_STAGE_BYTES + B_STAGE_BYTES)
#define GEMM_SMEM (NBUF*STAGE_BYTES + 1024)   // 66560

__global__ __launch_bounds__(256, 2) void gemm_act_kernel(
    const float* __restrict__ bz, const float* __restrict__ bh)
{
    extern __shared__ char dyn[];
    float* sBias = reinterpret_cast<float*>(dyn + NBUF * STAGE_BYTES);
    const uint32_t sbase = smem_u32(dyn);

    const int tid  = threadIdx.x;
    const int wid  = tid >> 5;
    const int lane = tid & 31;
    const int wm = wid >> 2;     // 0..1
    const int wn = wid & 3;      // 0..3

    const int bn = blockIdx.x;   // 0..7 over fused N=1024
    const int bm = blockIdx.y;   // 0..255
    const bool isZ = (bn < 4);
    const int nbase = (bn & 3) * 128;        // within 512-col output buffer
    const int m0 = bm * 128;
    const int mb0 = bm * 8;                  // first 16-row block
    const int nb0 = bn * 16;                 // first 8-col block (fused n space)

    if (tid < 128) sBias[tid] = isZ ? bz[nbase + tid] : bh[nbase + tid];

    float acc[4][4][4];
    #pragma unroll
    for (int i = 0; i < 4; i++)
        #pragma unroll
        for (int j = 0; j < 4; j++)
            #pragma unroll
            for (int q = 0; q < 4; q++) acc[i][j][q] = 0.f;

    // ---- stage loader: 16KB per stage, 256 threads x 4 iters x 16B ----
    auto load_stage = [&](int s, int buf) {
        const int kb0 = s * 2;
        const uint32_t stA = sbase + buf * STAGE_BYTES;
        const uint32_t stB = stA + A_STAGE_BYTES;
        // A: 512 segs of 16B; per m-block: 2 k-blocks = 1KB contiguous in gmem
        #pragma unroll
        for (int i = 0; i < 2; i++) {
            const int seg = tid + i * 256;
            const int mbi = seg >> 6;        // 64 segs per m-block
            const int w   = seg & 63;
            const float* gp = g_Xp + ((size_t)(mb0 + mbi) * 64 + kb0) * 128 + w * 4;
            CP_ASYNC16(stA + seg * 16, gp);
        }
        // B: 512 segs of 16B; per n-block: 2 k-blocks = 512B contiguous
        #pragma unroll
        for (int i = 0; i < 2; i++) {
            const int seg = tid + i * 256;
            const int nbi = seg >> 5;        // 32 segs per n-block
            const int w   = seg & 31;
            const float* gp = g_Wp + ((size_t)(nb0 + nbi) * 64 + kb0) * 64 + w * 4;
            CP_ASYNC16(stB + seg * 16, gp);
        }
    };

    // prologue
    load_stage(0, 0); CP_COMMIT();
    load_stage(1, 1); CP_COMMIT();
    load_stage(2, 2); CP_COMMIT();

    for (int s = 0; s < KSTAGES; s++) {
        CP_WAIT2();              // stage s resident
        __syncthreads();         // visible to all; all warps done with buf (s-1)&3
        if (s + 3 < KSTAGES) load_stage(s + 3, (s + 3) & 3);
        CP_COMMIT();             // empty group in tail keeps wait_group counting uniform

        const char* stA = dyn + ((s & 3) * STAGE_BYTES);
        const char* stB = stA + A_STAGE_BYTES;

        #pragma unroll
        for (int ks = 0; ks < 2; ks++) {
            uint32_t af[4][4];
            uint32_t bf[4][2];
            #pragma unroll
            for (int mt = 0; mt < 4; mt++) {
                const int mb = wm * 4 + mt;
                const uint4 v = *reinterpret_cast<const uint4*>(stA + (mb * 2 + ks) * 512 + lane * 16);
                af[mt][0] = v.x; af[mt][1] = v.y; af[mt][2] = v.z; af[mt][3] = v.w;
            }
            #pragma unroll
            for (int nt = 0; nt < 4; nt++) {
                const int nb = wn * 4 + nt;
                const uint2 v = *reinterpret_cast<const uint2*>(stB + (nb * 2 + ks) * 256 + lane * 8);
                bf[nt][0] = v.x; bf[nt][1] = v.y;
            }
            #pragma unroll
            for (int mt = 0; mt < 4; mt++)
                #pragma unroll
                for (int nt = 0; nt < 4; nt++)
                    mma_tf32(acc[mt][nt], af[mt], bf[nt]);
        }
    }

    // ---- epilogue: bias + activation ----
    float* __restrict__ outBuf = isZ ? g_C : g_G;
    const int row0 = m0 + wm * 64 + (lane >> 2);
    const int col0 = wn * 32 + 2 * (lane & 3);

    #pragma unroll
    for (int mt = 0; mt < 4; mt++) {
        #pragma unroll
        for (int nt = 0; nt < 4; nt++) {
            const int cl = col0 + nt * 8;          // 0..127 within tile
            const float b0v = sBias[cl];
            const float b1v = sBias[cl + 1];
            const int c = nbase + cl;
            #pragma unroll
            for (int half = 0; half < 2; half++) {
                const int rr = row0 + mt * 16 + half * 8;
                float v0 = acc[mt][nt][half * 2 + 0] + b0v;
                float v1 = acc[mt][nt][half * 2 + 1] + b1v;
                float o0, o1;
                if (isZ) {
                    o0 = sigmoidf_(-v0);
                    o1 = sigmoidf_(-v1);
                } else {
                    o0 = (v0 >= 0.f) ? (v0 + 0.5f) : sigmoidf_(v0);
                    o1 = (v1 >= 0.f) ? (v1 + 0.5f) : sigmoidf_(v1);
                }
                *reinterpret_cast<float2*>(&outBuf[(size_t)rr * H_ + c]) = make_float2(o0, o1);
            }
        }
    }
}

// ----------------------------- scan phase A: per-chunk reduce -----------------------------
__global__ __launch_bounds__(256) void scan_phaseA()
{
    const int idx = blockIdx.x * 256 + threadIdx.x;     // 0 .. 65535
    const int h4 = idx & 127;
    const int ch = (idx >> 7) & (NC - 1);
    const int b  = idx >> 13;
    const float4* C4 = reinterpret_cast<const float4*>(g_C);
    const float4* G4 = reinterpret_cast<const float4*>(g_G);
    size_t p = ((size_t)(b * T_ + ch * LC) * H_) / 4 + h4;

    float4 A = make_float4(1.f,1.f,1.f,1.f);
    float4 s = make_float4(0.f,0.f,0.f,0.f);
    #pragma unroll 4
    for (int t = 0; t < LC; t++, p += H_/4) {
        const float4 c = C4[p];
        const float4 g = G4[p];
        s.x = c.x*s.x + (1.f-c.x)*g.x;  A.x *= c.x;
        s.y = c.y*s.y + (1.f-c.y)*g.y;  A.y *= c.y;
        s.z = c.z*s.z + (1.f-c.z)*g.z;  A.z *= c.z;
        s.w = c.w*s.w + (1.f-c.w)*g.w;  A.w *= c.w;
    }
    reinterpret_cast<float4*>(g_A)[idx] = A;
    reinterpret_cast<float4*>(g_S)[idx] = s;
}

// ----------------------------- scan phase B: chunk combine -----------------------------
__global__ __launch_bounds__(256) void scan_phaseB(const float* __restrict__ h0)
{
    const int idx = blockIdx.x * 256 + threadIdx.x;     // 0 .. 1023
    const int b = idx >> 7;
    const int h4 = idx & 127;
    float4 v = reinterpret_cast<const float4*>(h0)[b * 128 + h4];
    float4 st;
    st.x = (v.x >= 0.f) ? (v.x + 0.5f) : sigmoidf_(v.x);
    st.y = (v.y >= 0.f) ? (v.y + 0.5f) : sigmoidf_(v.y);
    st.z = (v.z >= 0.f) ? (v.z + 0.5f) : sigmoidf_(v.z);
    st.w = (v.w >= 0.f) ? (v.w + 0.5f) : sigmoidf_(v.w);

    #pragma unroll 4
    for (int ch = 0; ch < NC; ch++) {
        const int o = (b * NC + ch) * 128 + h4;
        reinterpret_cast<float4*>(g_Hb)[o] = st;
        const float4 A = reinterpret_cast<const float4*>(g_A)[o];
        const float4 S = reinterpret_cast<const float4*>(g_S)[o];
        st.x = A.x*st.x + S.x;  st.y = A.y*st.y + S.y;
        st.z = A.z*st.z + S.z;  st.w = A.w*st.w + S.w;
    }
}

// ----------------------------- scan phase C: rescan + output -----------------------------
__global__ __launch_bounds__(256) void scan_phaseC(float* __restrict__ out)
{
    const int idx = blockIdx.x * 256 + threadIdx.x;
    const int h4 = idx & 127;
    const int ch = (idx >> 7) & (NC - 1);
    const int b  = idx >> 13;
    const float4* C4 = reinterpret_cast<const float4*>(g_C);
    const float4* G4 = reinterpret_cast<const float4*>(g_G);
    float4* O4 = reinterpret_cast<float4*>(out);
    size_t p = ((size_t)(b * T_ + ch * LC) * H_) / 4 + h4;

    float4 st = reinterpret_cast<const float4*>(g_Hb)[idx];
    #pragma unroll 4
    for (int t = 0; t < LC; t++, p += H_/4) {
        const float4 c = C4[p];
        const float4 g = G4[p];
        st.x = c.x*st.x + (1.f-c.x)*g.x;
        st.y = c.y*st.y + (1.f-c.y)*g.y;
        st.z = c.z*st.z + (1.f-c.z)*g.z;
        st.w = c.w*st.w + (1.f-c.w)*g.w;
        O4[p] = st;
    }
}

extern "C" void kernel_launch(void* const* d_in, const int* in_sizes, int n_in,
                              void* d_out, int out_size)
{
    const float* x  = (const float*)d_in[0];
    const float* h0 = (const float*)d_in[1];
    const float* Wz = (const float*)d_in[2];
    const float* bz = (const float*)d_in[3];
    const float* Wh = (const float*)d_in[4];
    const float* bh = (const float*)d_in[5];
    float* out = (float*)d_out;

    cudaFuncSetAttribute(gemm_act_kernel, cudaFuncAttributeMaxDynamicSharedMemorySize, GEMM_SMEM);

    prep_kernel<<<(XBLOCKS + WBLOCKS) / 8, 256>>>(x, Wz, Wh);
    gemm_act_kernel<<<dim3(8, 256), 256, GEMM_SMEM>>>(bz, bh);
    scan_phaseA<<<256, 256>>>();
    scan_phaseB<<<4, 256>>>(h0);
    scan_phaseC<<<256, 256>>>(out);
}